// round 11
// baseline (speedup 1.0000x reference)
#include <cuda_runtime.h>
#include <cuda_fp16.h>
#include <math.h>
#include <stdint.h>

#define NP 2048
#define EP 512
#define MT 4096

// ---------------- device scratch ----------------
__device__ __align__(16) float g_sin[NP*32];
__device__ __align__(16) float g_cos[NP*32];
__device__ __align__(16) float g_scale[NP*32];
__device__ __align__(16) __half g_INh[3][MT*EP];
__device__ __align__(16) __half g_INl[3][MT*EP];
__device__ __align__(16) __half g_Wh[5][EP*EP];
__device__ __align__(16) __half g_Qh[MT*EP], g_Ql[MT*EP];
__device__ __align__(16) __half g_Kh[MT*EP];
__device__ __align__(16) __half g_Vh[MT*EP];
__device__ __align__(16) __half g_RGh[MT*EP], g_RGl[MT*EP];
__device__ __align__(16) float g_G[MT*EP];

// ---------------- helpers ----------------
__device__ __forceinline__ uint32_t smem_u32(const void* p) {
    uint32_t a;
    asm("{ .reg .u64 t; cvta.to.shared.u64 t, %1; cvt.u32.u64 %0, t; }" : "=r"(a) : "l"(p));
    return a;
}
__device__ __forceinline__ void ldsm4(uint32_t* r, uint32_t a) {
    asm volatile("ldmatrix.sync.aligned.m8n8.x4.shared.b16 {%0,%1,%2,%3}, [%4];"
        : "=r"(r[0]), "=r"(r[1]), "=r"(r[2]), "=r"(r[3]) : "r"(a));
}
__device__ __forceinline__ void ldsm4t(uint32_t* r, uint32_t a) {
    asm volatile("ldmatrix.sync.aligned.m8n8.x4.trans.shared.b16 {%0,%1,%2,%3}, [%4];"
        : "=r"(r[0]), "=r"(r[1]), "=r"(r[2]), "=r"(r[3]) : "r"(a));
}
__device__ __forceinline__ void mma_f16(float* c, const uint32_t* a, uint32_t b0, uint32_t b1) {
    asm volatile("mma.sync.aligned.m16n8k16.row.col.f32.f16.f16.f32 "
        "{%0,%1,%2,%3}, {%4,%5,%6,%7}, {%8,%9}, {%0,%1,%2,%3};"
        : "+f"(c[0]), "+f"(c[1]), "+f"(c[2]), "+f"(c[3])
        : "r"(a[0]), "r"(a[1]), "r"(a[2]), "r"(a[3]), "r"(b0), "r"(b1));
}
__device__ __forceinline__ void split_pair_h(float v0, float v1, uint32_t& hi, uint32_t& lo) {
    __half h0 = __float2half_rn(v0);
    __half h1 = __float2half_rn(v1);
    __half l0 = __float2half_rn(v0 - __half2float(h0));
    __half l1 = __float2half_rn(v1 - __half2float(h1));
    __half2 H = __halves2half2(h0, h1);
    __half2 L = __halves2half2(l0, l1);
    hi = *reinterpret_cast<uint32_t*>(&H);
    lo = *reinterpret_cast<uint32_t*>(&L);
}
__device__ __forceinline__ uint32_t pack_h(float v0, float v1) {
    __half2 H = __floats2half2_rn(v0, v1);
    return *reinterpret_cast<uint32_t*>(&H);
}
__device__ __forceinline__ void cp16(uint32_t sdst, const void* gsrc) {
    asm volatile("cp.async.cg.shared.global [%0], [%1], 16;" :: "r"(sdst), "l"(gsrc) : "memory");
}
#define CP_COMMIT() asm volatile("cp.async.commit_group;" ::: "memory")
#define CP_WAIT(N)  asm volatile("cp.async.wait_group %0;" :: "n"(N) : "memory")

// ---------------- xpos tables ----------------
__global__ void build_tables() {
    int idx = blockIdx.x * 256 + threadIdx.x;
    if (idx >= NP*32) return;
    int n = idx >> 5, j = idx & 31;
    float inv_freq = expf(-(float)j * (9.210340371976184f / 32.f));
    float s, c;
    sincosf((float)n * inv_freq, &s, &c);
    float xscale = (2.f*(float)j + 25.6f) / 89.6f;
    float power = ((float)n - 1024.f) * (1.f/512.f);
    g_sin[idx] = s; g_cos[idx] = c; g_scale[idx] = expf(power * logf(xscale));
}

// ---------------- pre-split / convert ----------------
__global__ void convert_in(const float* __restrict__ q, const float* __restrict__ k,
                           const float* __restrict__ v) {
    int z = blockIdx.y;
    const float* src = (z == 0) ? q : (z == 1) ? k : v;
    int idx = (blockIdx.x * 256 + threadIdx.x) * 4;
    float4 x = *(const float4*)(src + idx);
    uint32_t h0,l0,h1,l1;
    split_pair_h(x.x, x.y, h0, l0);
    split_pair_h(x.z, x.w, h1, l1);
    *(uint2*)(&g_INh[z][idx]) = make_uint2(h0, h1);
    *(uint2*)(&g_INl[z][idx]) = make_uint2(l0, l1);
}
__global__ void convert_w(const float* __restrict__ w0, const float* __restrict__ w1,
                          const float* __restrict__ w2, const float* __restrict__ w3,
                          const float* __restrict__ w4) {
    int z = blockIdx.y;
    const float* src = (z == 0) ? w0 : (z == 1) ? w1 : (z == 2) ? w2 : (z == 3) ? w3 : w4;
    int idx = (blockIdx.x * 256 + threadIdx.x) * 4;
    float4 x = *(const float4*)(src + idx);
    *(uint2*)(&g_Wh[z][idx]) = make_uint2(pack_h(x.x, x.y), pack_h(x.z, x.w));
}

// ===== projection GEMM (fp16 x2, M64xN128 tile, warp 32x32, 3-stage K32, 3 CTA/SM) =====
// stage 20480B: AH@0 (64x80B) AL@5120 BH@10240 (128x80B)
#define PSTG 20480
#define PROJ_SMEM (3*PSTG)

__device__ __forceinline__ void proj_load_stage(
    uint32_t sb, int stage,
    const __half* __restrict__ Ah, const __half* __restrict__ Al,
    const __half* __restrict__ Bh,
    int m0, int n0, int kc, int tid)
{
    uint32_t s0 = sb + stage * PSTG;
    {   // A hi + lo: 64 rows x 4 segs, 256 threads -> 1 op each per plane
        int row = tid >> 2, seg = tid & 3;
        uint32_t so = (uint32_t)row*80 + seg*16;
        size_t ga = (size_t)(m0 + row)*EP + kc*32 + seg*8;
        cp16(s0 +         so, Ah + ga);
        cp16(s0 + 5120 +  so, Al + ga);
    }
    #pragma unroll
    for (int i = 0; i < 2; i++) {   // B hi: 128 rows x 4 segs = 512 ops
        int t = tid + i*256; int row = t >> 2, seg = t & 3;
        uint32_t so = (uint32_t)row*80 + seg*16;
        size_t gb = (size_t)(n0 + row)*EP + kc*32 + seg*8;
        cp16(s0 + 10240 + so, Bh + gb);
    }
}

__device__ __forceinline__ void proj_body(
    const __half* __restrict__ Ah, const __half* __restrict__ Al,
    const __half* __restrict__ Bh,
    const float* __restrict__ bias, int epi,
    float* Cf, __half* Ch, __half* Cl, char* sm)
{
    const int tid = threadIdx.x, lane = tid & 31, wid = tid >> 5;
    const int wm = wid & 1, wn = wid >> 1;          // 2 m-warps x 4 n-warps
    const int n0 = blockIdx.x * 128, m0 = blockIdx.y * 64;
    const uint32_t sb = smem_u32(sm);
    float acc[2][4][4] = {};

    proj_load_stage(sb, 0, Ah, Al, Bh, m0, n0, 0, tid); CP_COMMIT();
    proj_load_stage(sb, 1, Ah, Al, Bh, m0, n0, 1, tid); CP_COMMIT();

    for (int kc = 0; kc < 16; kc++) {
        CP_WAIT(1);
        __syncthreads();
        if (kc + 2 < 16)
            proj_load_stage(sb, (kc + 2) % 3, Ah, Al, Bh, m0, n0, kc + 2, tid);
        CP_COMMIT();

        const uint32_t base = sb + (kc % 3) * PSTG;
        #pragma unroll
        for (int kk = 0; kk < 2; kk++) {
            uint32_t ah[2][4], al[2][4];
            #pragma unroll
            for (int mt = 0; mt < 2; mt++) {
                uint32_t off = (uint32_t)(wm*32 + mt*16 + (lane & 15))*80 + kk*32 + ((lane >> 4) & 1)*16;
                ldsm4(ah[mt], base + off);
                ldsm4(al[mt], base + 5120 + off);
            }
            uint32_t bh[2][4];
            #pragma unroll
            for (int jt = 0; jt < 2; jt++) {
                uint32_t off = (uint32_t)(wn*32 + jt*16 + (lane & 7) + ((lane & 16) ? 8 : 0))*80
                             + kk*32 + ((lane & 8) ? 16 : 0);
                ldsm4(bh[jt], base + 10240 + off);
            }
            #pragma unroll
            for (int mt = 0; mt < 2; mt++)
                #pragma unroll
                for (int nt = 0; nt < 4; nt++) {
                    int jt = nt >> 1, o = (nt & 1)*2;
                    mma_f16(acc[mt][nt], ah[mt], bh[jt][o], bh[jt][o+1]);
                    mma_f16(acc[mt][nt], al[mt], bh[jt][o], bh[jt][o+1]);
                }
        }
    }

    #pragma unroll
    for (int mt = 0; mt < 2; mt++) {
        #pragma unroll
        for (int rr = 0; rr < 2; rr++) {
            int row = m0 + wm*32 + mt*16 + (lane >> 2) + rr*8;
            int npos = row & (NP - 1);
            #pragma unroll
            for (int nt = 0; nt < 4; nt++) {
                int col = n0 + wn*32 + nt*8 + 2*(lane & 3);
                float x0 = acc[mt][nt][rr*2]     + bias[col];
                float x1 = acc[mt][nt][rr*2 + 1] + bias[col + 1];
                if (epi == 1) {
                    x0 = x0 / (1.f + expf(-x0));
                    x1 = x1 / (1.f + expf(-x1));
                } else if (epi == 2 || epi == 3) {
                    int j2 = (col & 63) >> 1;
                    float sn = g_sin[npos*32 + j2];
                    float cs = g_cos[npos*32 + j2];
                    float sc = g_scale[npos*32 + j2];
                    if (epi == 3) sc = 1.f / sc;
                    float s = sn * sc, c = cs * sc;
                    float y0 = x0 * c - x1 * s;
                    float y1 = x1 * c + x0 * s;
                    if (epi == 3) { y0 *= 0.125f; y1 *= 0.125f; }
                    x0 = y0; x1 = y1;
                }
                size_t off = (size_t)row*EP + col;
                if (Cf) {
                    *(float2*)(Cf + off) = make_float2(x0, x1);
                } else if (Cl) {
                    uint32_t hh, ll;
                    split_pair_h(x0, x1, hh, ll);
                    *(uint32_t*)(Ch + off) = hh;
                    *(uint32_t*)(Cl + off) = ll;
                } else {
                    *(uint32_t*)(Ch + off) = pack_h(x0, x1);
                }
            }
        }
    }
}

__global__ void __launch_bounds__(256, 3) qkvg_kernel(
    const float* __restrict__ bq, const float* __restrict__ bk,
    const float* __restrict__ bv, const float* __restrict__ bg)
{
    extern __shared__ char sm[];
    const int z = blockIdx.z;
    const __half* Ah = g_INh[(z == 3) ? 0 : z];
    const __half* Al = g_INl[(z == 3) ? 0 : z];
    const float* bias = (z == 0) ? bq : (z == 1) ? bk : (z == 2) ? bv : bg;
    __half* Ch = (z == 0) ? g_Qh : (z == 1) ? g_Kh : (z == 2) ? g_Vh : (__half*)0;
    __half* Cl = (z == 0) ? g_Ql : (__half*)0;
    float* Cf = (z == 3) ? g_G : (float*)0;
    const int epi = (z == 0) ? 2 : (z == 1) ? 3 : (z == 2) ? 0 : 1;
    proj_body(Ah, Al, g_Wh[z], bias, epi, Cf, Ch, Cl, sm);
}

__global__ void __launch_bounds__(256, 3) out_kernel(const float* __restrict__ bo,
                                                     float* __restrict__ out)
{
    extern __shared__ char sm[];
    proj_body(g_RGh, g_RGl, g_Wh[4], bo, 0, out, (__half*)0, (__half*)0, sm);
}

// ========== retention (fp16 x2, 64-row q-tiles, 128 thr, 2-stage KV, 4 CTA/SM) ====
// smem: QH@0 (64x144) QL@9216 | KV stage s @ 18432+s*18432 {KH+0, VH+9216}
#define RSM_QH 0u
#define RSM_QL 9216u
#define RSM_KV 18432u
#define KVSTG 18432u
#define RET_SMEM (18432u + 2u*18432u)   // 55296

__device__ __forceinline__ void kv_load_stage(uint32_t sb, int stage, int b, int h,
                                              int st, int tid)
{
    uint32_t s0 = sb + RSM_KV + (uint32_t)stage * KVSTG;
    #pragma unroll
    for (int i = 0; i < 4; i++) {
        int t = tid + i*128; int row = t >> 3, seg = t & 7;
        uint32_t so = (uint32_t)row*144 + seg*16;
        size_t ga = (size_t)(b*NP + st*64 + row)*EP + h*64 + seg*8;
        cp16(s0 +        so, g_Kh + ga);
        cp16(s0 + 9216 + so, g_Vh + ga);
    }
}

__global__ void __launch_bounds__(128, 4) retention_kernel()
{
    extern __shared__ char sm[];
    const int tid = threadIdx.x, lane = tid & 31, wid = tid >> 5;   // wid 0..3
    const int h = blockIdx.y, b = blockIdx.z;
    const uint32_t sb = smem_u32(sm);

    const float gamma = 1.f - expf(-(3.465735902799726f + 0.396084103177426f * (float)h));
    const float l2g = log2f(gamma);

    float colf[16];
    #pragma unroll
    for (int nt = 0; nt < 8; nt++) {
        int sl = nt*8 + 2*(lane & 3);
        colf[nt*2]   = exp2f(-l2g * (float)sl);
        colf[nt*2+1] = exp2f(-l2g * (float)(sl + 1));
    }
    const int nl0 = wid*16 + (lane >> 2);

    for (int phase = 0; phase < 2; phase++) {
        const int qt = phase ? (int)blockIdx.x : 31 - (int)blockIdx.x;
        const int n_st = qt + 1;

        // load Q tile (64 x 64, hi/lo fp16)
        #pragma unroll
        for (int i = 0; i < 4; i++) {
            int t = tid + i*128; int row = t >> 3, seg = t & 7;
            size_t ga = (size_t)(b*NP + qt*64 + row)*EP + h*64 + seg*8;
            *(uint4*)(sm + RSM_QH + row*144 + seg*16) = *(const uint4*)(g_Qh + ga);
            *(uint4*)(sm + RSM_QL + row*144 + seg*16) = *(const uint4*)(g_Ql + ga);
        }
        __syncthreads();   // prev-phase compute done + Q visible

        kv_load_stage(sb, 0, b, h, 0, tid); CP_COMMIT();

        uint32_t qh[4][4], ql[4][4];
        #pragma unroll
        for (int kk = 0; kk < 4; kk++) {
            uint32_t off = (uint32_t)(wid*16 + (lane & 15))*144 + kk*32 + ((lane >> 4) & 1)*16;
            ldsm4(qh[kk], sb + RSM_QH + off);
            ldsm4(ql[kk], sb + RSM_QL + off);
        }

        float ret[8][4] = {};

        for (int st = 0; st < n_st; st++) {
            CP_WAIT(0);
            __syncthreads();   // stage (st&1) ready; all warps done reading (st+1)&1
            if (st + 1 < n_st) kv_load_stage(sb, (st + 1) & 1, b, h, st + 1, tid);
            CP_COMMIT();

            const uint32_t kvb = sb + RSM_KV + (uint32_t)(st & 1) * KVSTG;

            // gemm1: sim = Q K^T (k = 64)
            float simf[8][4] = {};
            #pragma unroll
            for (int kk = 0; kk < 4; kk++) {
                uint32_t bh[4][4];
                #pragma unroll
                for (int jt = 0; jt < 4; jt++) {
                    uint32_t off = (uint32_t)(jt*16 + (lane & 7) + ((lane & 16) ? 8 : 0))*144
                                 + kk*32 + ((lane & 8) ? 16 : 0);
                    ldsm4(bh[jt], kvb + off);
                }
                #pragma unroll
                for (int nt = 0; nt < 8; nt++) {
                    int jt = nt >> 1, o = (nt & 1)*2;
                    mma_f16(simf[nt], qh[kk], bh[jt][o], bh[jt][o+1]);
                    mma_f16(simf[nt], ql[kk], bh[jt][o], bh[jt][o+1]);
                }
            }

            // decay + mask + split -> fp16 A-fragments of gemm2 (registers only)
            const int db = qt*64 - st*64;
            const float brf0 = exp2f(l2g * (float)(db + nl0));
            const float brf1 = exp2f(l2g * (float)(db + nl0 + 8));
            uint32_t pa_h[8], pa_l[8], pb_h[8], pb_l[8];
            #pragma unroll
            for (int nt = 0; nt < 8; nt++) {
                int sl0 = nt*8 + 2*(lane & 3);
                float v00 = (db + nl0 - sl0     >= 0) ? simf[nt][0]*brf0*colf[nt*2]   : 0.f;
                float v01 = (db + nl0 - sl0 - 1 >= 0) ? simf[nt][1]*brf0*colf[nt*2+1] : 0.f;
                float v10 = (db + nl0 + 8 - sl0     >= 0) ? simf[nt][2]*brf1*colf[nt*2]   : 0.f;
                float v11 = (db + nl0 + 8 - sl0 - 1 >= 0) ? simf[nt][3]*brf1*colf[nt*2+1] : 0.f;
                split_pair_h(v00, v01, pa_h[nt], pa_l[nt]);
                split_pair_h(v10, v11, pb_h[nt], pb_l[nt]);
            }

            // gemm2: ret += sim @ V
            #pragma unroll
            for (int kk = 0; kk < 4; kk++) {
                uint32_t ah2[4] = { pa_h[2*kk], pb_h[2*kk], pa_h[2*kk+1], pb_h[2*kk+1] };
                uint32_t al2[4] = { pa_l[2*kk], pb_l[2*kk], pa_l[2*kk+1], pb_l[2*kk+1] };
                uint32_t bh[4][4];
                #pragma unroll
                for (int dt = 0; dt < 4; dt++) {
                    uint32_t off = (uint32_t)(kk*16 + (lane & 15))*144 + dt*32 + ((lane >> 4) & 1)*16;
                    ldsm4t(bh[dt], kvb + 9216 + off);
                }
                #pragma unroll
                for (int nt = 0; nt < 8; nt++) {
                    int dt = nt >> 1, o = (nt & 1)*2;
                    mma_f16(ret[nt], ah2, bh[dt][o], bh[dt][o+1]);
                    mma_f16(ret[nt], al2, bh[dt][o], bh[dt][o+1]);
                }
            }
        }

        // groupnorm + gate + write hi/lo fp16 planes
        #pragma unroll
        for (int rr = 0; rr < 2; rr++) {
            float s1 = 0.f, s2 = 0.f;
            #pragma unroll
            for (int nt = 0; nt < 8; nt++) {
                float a = ret[nt][rr*2], c = ret[nt][rr*2+1];
                s1 += a + c; s2 += a*a + c*c;
            }
            s1 += __shfl_xor_sync(0xffffffffu, s1, 1); s2 += __shfl_xor_sync(0xffffffffu, s2, 1);
            s1 += __shfl_xor_sync(0xffffffffu, s1, 2); s2 += __shfl_xor_sync(0xffffffffu, s2, 2);
            float mean = s1 * (1.f/64.f);
            float var  = s2 * (1.f/64.f) - mean*mean;
            float inv  = rsqrtf(var + 1e-6f);
            int row = qt*64 + nl0 + rr*8;
            size_t base = (size_t)(b*NP + row)*EP + h*64;
            #pragma unroll
            for (int nt = 0; nt < 8; nt++) {
                int col = nt*8 + 2*(lane & 3);
                float2 g2 = *(const float2*)(g_G + base + col);
                float x0 = (ret[nt][rr*2]   - mean)*inv * g2.x;
                float x1 = (ret[nt][rr*2+1] - mean)*inv * g2.y;
                uint32_t hh, ll;
                split_pair_h(x0, x1, hh, ll);
                *(uint32_t*)(g_RGh + base + col) = hh;
                *(uint32_t*)(g_RGl + base + col) = ll;
            }
        }
    }
}

// ---------------- launch ----------------
extern "C" void kernel_launch(void* const* d_in, const int* in_sizes, int n_in,
                              void* d_out, int out_size) {
    const float* query = (const float*)d_in[0];
    const float* key   = (const float*)d_in[1];
    const float* value = (const float*)d_in[2];
    const float* Wq = (const float*)d_in[3];
    const float* bq = (const float*)d_in[4];
    const float* Wk = (const float*)d_in[5];
    const float* bk = (const float*)d_in[6];
    const float* Wv = (const float*)d_in[7];
    const float* bv = (const float*)d_in[8];
    const float* Wg = (const float*)d_in[9];
    const float* bg = (const float*)d_in[10];
    const float* Wo = (const float*)d_in[11];
    const float* bo = (const float*)d_in[12];
    float* out = (float*)d_out;

    build_tables<<<(NP*32)/256, 256>>>();
    convert_in<<<dim3((MT*EP)/1024, 3), 256>>>(query, key, value);
    convert_w<<<dim3((EP*EP)/1024, 5), 256>>>(Wq, Wk, Wv, Wg, Wo);

    cudaFuncSetAttribute(qkvg_kernel, cudaFuncAttributeMaxDynamicSharedMemorySize, PROJ_SMEM);
    cudaFuncSetAttribute(out_kernel,  cudaFuncAttributeMaxDynamicSharedMemorySize, PROJ_SMEM);
    cudaFuncSetAttribute(retention_kernel, cudaFuncAttributeMaxDynamicSharedMemorySize, (int)RET_SMEM);

    qkvg_kernel<<<dim3(4, 64, 4), 256, PROJ_SMEM>>>(bq, bk, bv, bg);
    retention_kernel<<<dim3(16, 8, 2), 128, RET_SMEM>>>();
    out_kernel<<<dim3(4, 64, 1), 256, PROJ_SMEM>>>(bo, out);
}

// round 12
// speedup vs baseline: 1.2337x; 1.2337x over previous
#include <cuda_runtime.h>
#include <cuda_fp16.h>
#include <math.h>
#include <stdint.h>

#define NP 2048
#define EP 512
#define MT 4096

// ---------------- device scratch ----------------
__device__ __align__(16) float g_sin[NP*32];
__device__ __align__(16) float g_cos[NP*32];
__device__ __align__(16) float g_scale[NP*32];
__device__ __align__(16) __half g_INh[3][MT*EP];
__device__ __align__(16) __half g_INl[3][MT*EP];
__device__ __align__(16) __half g_Wh[5][EP*EP];
__device__ __align__(16) __half g_Qh[MT*EP];
__device__ __align__(16) __half g_Kh[MT*EP];
__device__ __align__(16) __half g_Vh[MT*EP];
__device__ __align__(16) __half g_RGh[MT*EP], g_RGl[MT*EP];
__device__ __align__(16) float g_G[MT*EP];

// ---------------- helpers ----------------
__device__ __forceinline__ uint32_t smem_u32(const void* p) {
    uint32_t a;
    asm("{ .reg .u64 t; cvta.to.shared.u64 t, %1; cvt.u32.u64 %0, t; }" : "=r"(a) : "l"(p));
    return a;
}
__device__ __forceinline__ void ldsm4(uint32_t* r, uint32_t a) {
    asm volatile("ldmatrix.sync.aligned.m8n8.x4.shared.b16 {%0,%1,%2,%3}, [%4];"
        : "=r"(r[0]), "=r"(r[1]), "=r"(r[2]), "=r"(r[3]) : "r"(a));
}
__device__ __forceinline__ void ldsm4t(uint32_t* r, uint32_t a) {
    asm volatile("ldmatrix.sync.aligned.m8n8.x4.trans.shared.b16 {%0,%1,%2,%3}, [%4];"
        : "=r"(r[0]), "=r"(r[1]), "=r"(r[2]), "=r"(r[3]) : "r"(a));
}
__device__ __forceinline__ void mma_f16(float* c, const uint32_t* a, uint32_t b0, uint32_t b1) {
    asm volatile("mma.sync.aligned.m16n8k16.row.col.f32.f16.f16.f32 "
        "{%0,%1,%2,%3}, {%4,%5,%6,%7}, {%8,%9}, {%0,%1,%2,%3};"
        : "+f"(c[0]), "+f"(c[1]), "+f"(c[2]), "+f"(c[3])
        : "r"(a[0]), "r"(a[1]), "r"(a[2]), "r"(a[3]), "r"(b0), "r"(b1));
}
__device__ __forceinline__ void split_pair_h(float v0, float v1, uint32_t& hi, uint32_t& lo) {
    __half h0 = __float2half_rn(v0);
    __half h1 = __float2half_rn(v1);
    __half l0 = __float2half_rn(v0 - __half2float(h0));
    __half l1 = __float2half_rn(v1 - __half2float(h1));
    __half2 H = __halves2half2(h0, h1);
    __half2 L = __halves2half2(l0, l1);
    hi = *reinterpret_cast<uint32_t*>(&H);
    lo = *reinterpret_cast<uint32_t*>(&L);
}
__device__ __forceinline__ uint32_t pack_h(float v0, float v1) {
    __half2 H = __floats2half2_rn(v0, v1);
    return *reinterpret_cast<uint32_t*>(&H);
}
__device__ __forceinline__ void cp16(uint32_t sdst, const void* gsrc) {
    asm volatile("cp.async.cg.shared.global [%0], [%1], 16;" :: "r"(sdst), "l"(gsrc) : "memory");
}
#define CP_COMMIT() asm volatile("cp.async.commit_group;" ::: "memory")
#define CP_WAIT(N)  asm volatile("cp.async.wait_group %0;" :: "n"(N) : "memory")

// ---------------- xpos tables ----------------
__global__ void build_tables() {
    int idx = blockIdx.x * 256 + threadIdx.x;
    if (idx >= NP*32) return;
    int n = idx >> 5, j = idx & 31;
    float inv_freq = expf(-(float)j * (9.210340371976184f / 32.f));
    float s, c;
    sincosf((float)n * inv_freq, &s, &c);
    float xscale = (2.f*(float)j + 25.6f) / 89.6f;
    float power = ((float)n - 1024.f) * (1.f/512.f);
    g_sin[idx] = s; g_cos[idx] = c; g_scale[idx] = expf(power * logf(xscale));
}

// ---------------- pre-split / convert ----------------
__global__ void convert_in(const float* __restrict__ q, const float* __restrict__ k,
                           const float* __restrict__ v) {
    int z = blockIdx.y;
    const float* src = (z == 0) ? q : (z == 1) ? k : v;
    int idx = (blockIdx.x * 256 + threadIdx.x) * 4;
    float4 x = *(const float4*)(src + idx);
    uint32_t h0,l0,h1,l1;
    split_pair_h(x.x, x.y, h0, l0);
    split_pair_h(x.z, x.w, h1, l1);
    *(uint2*)(&g_INh[z][idx]) = make_uint2(h0, h1);
    *(uint2*)(&g_INl[z][idx]) = make_uint2(l0, l1);
}
__global__ void convert_w(const float* __restrict__ w0, const float* __restrict__ w1,
                          const float* __restrict__ w2, const float* __restrict__ w3,
                          const float* __restrict__ w4) {
    int z = blockIdx.y;
    const float* src = (z == 0) ? w0 : (z == 1) ? w1 : (z == 2) ? w2 : (z == 3) ? w3 : w4;
    int idx = (blockIdx.x * 256 + threadIdx.x) * 4;
    float4 x = *(const float4*)(src + idx);
    *(uint2*)(&g_Wh[z][idx]) = make_uint2(pack_h(x.x, x.y), pack_h(x.z, x.w));
}

// ===== projection GEMM (fp16 x2, M64xN128 tile, warp 32x32, 3-stage K32, 3 CTA/SM) =====
// stage 20480B: AH@0 (64x80B) AL@5120 BH@10240 (128x80B)
#define PSTG 20480
#define PROJ_SMEM (3*PSTG)

__device__ __forceinline__ void proj_load_stage(
    uint32_t sb, int stage,
    const __half* __restrict__ Ah, const __half* __restrict__ Al,
    const __half* __restrict__ Bh,
    int m0, int n0, int kc, int tid)
{
    uint32_t s0 = sb + stage * PSTG;
    {   // A hi + lo: 64 rows x 4 segs, 256 threads -> 1 op each per plane
        int row = tid >> 2, seg = tid & 3;
        uint32_t so = (uint32_t)row*80 + seg*16;
        size_t ga = (size_t)(m0 + row)*EP + kc*32 + seg*8;
        cp16(s0 +         so, Ah + ga);
        cp16(s0 + 5120 +  so, Al + ga);
    }
    #pragma unroll
    for (int i = 0; i < 2; i++) {   // B hi: 128 rows x 4 segs = 512 ops
        int t = tid + i*256; int row = t >> 2, seg = t & 3;
        uint32_t so = (uint32_t)row*80 + seg*16;
        size_t gb = (size_t)(n0 + row)*EP + kc*32 + seg*8;
        cp16(s0 + 10240 + so, Bh + gb);
    }
}

__device__ __forceinline__ void proj_body(
    const __half* __restrict__ Ah, const __half* __restrict__ Al,
    const __half* __restrict__ Bh,
    const float* __restrict__ bias, int epi,
    float* Cf, __half* Ch, __half* Cl, char* sm)
{
    const int tid = threadIdx.x, lane = tid & 31, wid = tid >> 5;
    const int wm = wid & 1, wn = wid >> 1;          // 2 m-warps x 4 n-warps
    const int n0 = blockIdx.x * 128, m0 = blockIdx.y * 64;
    const uint32_t sb = smem_u32(sm);
    float acc[2][4][4] = {};

    proj_load_stage(sb, 0, Ah, Al, Bh, m0, n0, 0, tid); CP_COMMIT();
    proj_load_stage(sb, 1, Ah, Al, Bh, m0, n0, 1, tid); CP_COMMIT();

    for (int kc = 0; kc < 16; kc++) {
        CP_WAIT(1);
        __syncthreads();
        if (kc + 2 < 16)
            proj_load_stage(sb, (kc + 2) % 3, Ah, Al, Bh, m0, n0, kc + 2, tid);
        CP_COMMIT();

        const uint32_t base = sb + (kc % 3) * PSTG;
        #pragma unroll
        for (int kk = 0; kk < 2; kk++) {
            uint32_t ah[2][4], al[2][4];
            #pragma unroll
            for (int mt = 0; mt < 2; mt++) {
                uint32_t off = (uint32_t)(wm*32 + mt*16 + (lane & 15))*80 + kk*32 + ((lane >> 4) & 1)*16;
                ldsm4(ah[mt], base + off);
                ldsm4(al[mt], base + 5120 + off);
            }
            uint32_t bh[2][4];
            #pragma unroll
            for (int jt = 0; jt < 2; jt++) {
                uint32_t off = (uint32_t)(wn*32 + jt*16 + (lane & 7) + ((lane & 16) ? 8 : 0))*80
                             + kk*32 + ((lane & 8) ? 16 : 0);
                ldsm4(bh[jt], base + 10240 + off);
            }
            #pragma unroll
            for (int mt = 0; mt < 2; mt++)
                #pragma unroll
                for (int nt = 0; nt < 4; nt++) {
                    int jt = nt >> 1, o = (nt & 1)*2;
                    mma_f16(acc[mt][nt], ah[mt], bh[jt][o], bh[jt][o+1]);
                    mma_f16(acc[mt][nt], al[mt], bh[jt][o], bh[jt][o+1]);
                }
        }
    }

    #pragma unroll
    for (int mt = 0; mt < 2; mt++) {
        #pragma unroll
        for (int rr = 0; rr < 2; rr++) {
            int row = m0 + wm*32 + mt*16 + (lane >> 2) + rr*8;
            int npos = row & (NP - 1);
            #pragma unroll
            for (int nt = 0; nt < 4; nt++) {
                int col = n0 + wn*32 + nt*8 + 2*(lane & 3);
                float x0 = acc[mt][nt][rr*2]     + bias[col];
                float x1 = acc[mt][nt][rr*2 + 1] + bias[col + 1];
                if (epi == 1) {
                    x0 = x0 / (1.f + expf(-x0));
                    x1 = x1 / (1.f + expf(-x1));
                } else if (epi == 2 || epi == 3) {
                    int j2 = (col & 63) >> 1;
                    float sn = g_sin[npos*32 + j2];
                    float cs = g_cos[npos*32 + j2];
                    float sc = g_scale[npos*32 + j2];
                    if (epi == 3) sc = 1.f / sc;
                    float s = sn * sc, c = cs * sc;
                    float y0 = x0 * c - x1 * s;
                    float y1 = x1 * c + x0 * s;
                    if (epi == 3) { y0 *= 0.125f; y1 *= 0.125f; }
                    x0 = y0; x1 = y1;
                }
                size_t off = (size_t)row*EP + col;
                if (Cf) {
                    *(float2*)(Cf + off) = make_float2(x0, x1);
                } else if (Cl) {
                    uint32_t hh, ll;
                    split_pair_h(x0, x1, hh, ll);
                    *(uint32_t*)(Ch + off) = hh;
                    *(uint32_t*)(Cl + off) = ll;
                } else {
                    *(uint32_t*)(Ch + off) = pack_h(x0, x1);
                }
            }
        }
    }
}

__global__ void __launch_bounds__(256, 3) qkvg_kernel(
    const float* __restrict__ bq, const float* __restrict__ bk,
    const float* __restrict__ bv, const float* __restrict__ bg)
{
    extern __shared__ char sm[];
    const int z = blockIdx.z;
    const __half* Ah = g_INh[(z == 3) ? 0 : z];
    const __half* Al = g_INl[(z == 3) ? 0 : z];
    const float* bias = (z == 0) ? bq : (z == 1) ? bk : (z == 2) ? bv : bg;
    __half* Ch = (z == 0) ? g_Qh : (z == 1) ? g_Kh : (z == 2) ? g_Vh : (__half*)0;
    float* Cf = (z == 3) ? g_G : (float*)0;
    const int epi = (z == 0) ? 2 : (z == 1) ? 3 : (z == 2) ? 0 : 1;
    proj_body(Ah, Al, g_Wh[z], bias, epi, Cf, Ch, (__half*)0, sm);
}

__global__ void __launch_bounds__(256, 3) out_kernel(const float* __restrict__ bo,
                                                     float* __restrict__ out)
{
    extern __shared__ char sm[];
    proj_body(g_RGh, g_RGl, g_Wh[4], bo, 0, out, (__half*)0, (__half*)0, sm);
}

// ========== retention (fp16 single-plane mma, 64-row q-tiles, 3-stage KV, 3 CTA/SM) ====
// smem: QH@0 (64x144) | KV stage s @ 9216+s*18432 {KH+0, VH+9216}
#define RSM_QH 0u
#define RSM_KV 9216u
#define KVSTG 18432u
#define RET_SMEM (9216u + 3u*18432u)   // 64512

__device__ __forceinline__ void kv_load_stage(uint32_t sb, int stage, int b, int h,
                                              int st, int tid)
{
    uint32_t s0 = sb + RSM_KV + (uint32_t)stage * KVSTG;
    #pragma unroll
    for (int i = 0; i < 4; i++) {
        int t = tid + i*128; int row = t >> 3, seg = t & 7;
        uint32_t so = (uint32_t)row*144 + seg*16;
        size_t ga = (size_t)(b*NP + st*64 + row)*EP + h*64 + seg*8;
        cp16(s0 +        so, g_Kh + ga);
        cp16(s0 + 9216 + so, g_Vh + ga);
    }
}

__global__ void __launch_bounds__(128, 3) retention_kernel()
{
    extern __shared__ char sm[];
    const int tid = threadIdx.x, lane = tid & 31, wid = tid >> 5;   // wid 0..3
    const int h = blockIdx.y, b = blockIdx.z;
    const uint32_t sb = smem_u32(sm);

    const float gamma = 1.f - expf(-(3.465735902799726f + 0.396084103177426f * (float)h));
    const float l2g = log2f(gamma);

    float colf[16];
    #pragma unroll
    for (int nt = 0; nt < 8; nt++) {
        int sl = nt*8 + 2*(lane & 3);
        colf[nt*2]   = exp2f(-l2g * (float)sl);
        colf[nt*2+1] = exp2f(-l2g * (float)(sl + 1));
    }
    const int nl0 = wid*16 + (lane >> 2);

    for (int phase = 0; phase < 2; phase++) {
        const int qt = phase ? (int)blockIdx.x : 31 - (int)blockIdx.x;
        const int n_st = qt + 1;

        // load Q tile (64 x 64, fp16 single plane)
        #pragma unroll
        for (int i = 0; i < 4; i++) {
            int t = tid + i*128; int row = t >> 3, seg = t & 7;
            size_t ga = (size_t)(b*NP + qt*64 + row)*EP + h*64 + seg*8;
            *(uint4*)(sm + RSM_QH + row*144 + seg*16) = *(const uint4*)(g_Qh + ga);
        }
        __syncthreads();   // prev-phase compute done + Q visible

        kv_load_stage(sb, 0, b, h, 0, tid); CP_COMMIT();
        if (n_st > 1) kv_load_stage(sb, 1, b, h, 1, tid);
        CP_COMMIT();

        uint32_t qh[4][4];
        #pragma unroll
        for (int kk = 0; kk < 4; kk++) {
            uint32_t off = (uint32_t)(wid*16 + (lane & 15))*144 + kk*32 + ((lane >> 4) & 1)*16;
            ldsm4(qh[kk], sb + RSM_QH + off);
        }

        float ret[8][4] = {};

        for (int st = 0; st < n_st; st++) {
            CP_WAIT(1);
            __syncthreads();
            if (st + 2 < n_st) kv_load_stage(sb, (st + 2) % 3, b, h, st + 2, tid);
            CP_COMMIT();

            const uint32_t kvb = sb + RSM_KV + (uint32_t)(st % 3) * KVSTG;

            // gemm1: sim = Q K^T (k = 64), fp16 single plane
            float simf[8][4] = {};
            #pragma unroll
            for (int kk = 0; kk < 4; kk++) {
                uint32_t bh[4][4];
                #pragma unroll
                for (int jt = 0; jt < 4; jt++) {
                    uint32_t off = (uint32_t)(jt*16 + (lane & 7) + ((lane & 16) ? 8 : 0))*144
                                 + kk*32 + ((lane & 8) ? 16 : 0);
                    ldsm4(bh[jt], kvb + off);
                }
                #pragma unroll
                for (int nt = 0; nt < 8; nt++) {
                    int jt = nt >> 1, o = (nt & 1)*2;
                    mma_f16(simf[nt], qh[kk], bh[jt][o], bh[jt][o+1]);
                }
            }

            // decay + mask + pack -> fp16 A-fragments of gemm2 (registers only)
            const int db = qt*64 - st*64;
            const float brf0 = exp2f(l2g * (float)(db + nl0));
            const float brf1 = exp2f(l2g * (float)(db + nl0 + 8));
            uint32_t pa[8], pb[8];
            #pragma unroll
            for (int nt = 0; nt < 8; nt++) {
                int sl0 = nt*8 + 2*(lane & 3);
                float v00 = (db + nl0 - sl0     >= 0) ? simf[nt][0]*brf0*colf[nt*2]   : 0.f;
                float v01 = (db + nl0 - sl0 - 1 >= 0) ? simf[nt][1]*brf0*colf[nt*2+1] : 0.f;
                float v10 = (db + nl0 + 8 - sl0     >= 0) ? simf[nt][2]*brf1*colf[nt*2]   : 0.f;
                float v11 = (db + nl0 + 8 - sl0 - 1 >= 0) ? simf[nt][3]*brf1*colf[nt*2+1] : 0.f;
                pa[nt] = pack_h(v00, v01);
                pb[nt] = pack_h(v10, v11);
            }

            // gemm2: ret += sim @ V (fp16 single plane)
            #pragma unroll
            for (int kk = 0; kk < 4; kk++) {
                uint32_t ah2[4] = { pa[2*kk], pb[2*kk], pa[2*kk+1], pb[2*kk+1] };
                uint32_t bh[4][4];
                #pragma unroll
                for (int dt = 0; dt < 4; dt++) {
                    uint32_t off = (uint32_t)(kk*16 + (lane & 15))*144 + dt*32 + ((lane >> 4) & 1)*16;
                    ldsm4t(bh[dt], kvb + 9216 + off);
                }
                #pragma unroll
                for (int nt = 0; nt < 8; nt++) {
                    int dt = nt >> 1, o = (nt & 1)*2;
                    mma_f16(ret[nt], ah2, bh[dt][o], bh[dt][o+1]);
                }
            }
        }

        // groupnorm + gate + write hi/lo fp16 planes
        #pragma unroll
        for (int rr = 0; rr < 2; rr++) {
            float s1 = 0.f, s2 = 0.f;
            #pragma unroll
            for (int nt = 0; nt < 8; nt++) {
                float a = ret[nt][rr*2], c = ret[nt][rr*2+1];
                s1 += a + c; s2 += a*a + c*c;
            }
            s1 += __shfl_xor_sync(0xffffffffu, s1, 1); s2 += __shfl_xor_sync(0xffffffffu, s2, 1);
            s1 += __shfl_xor_sync(0xffffffffu, s1, 2); s2 += __shfl_xor_sync(0xffffffffu, s2, 2);
            float mean = s1 * (1.f/64.f);
            float var  = s2 * (1.f/64.f) - mean*mean;
            float inv  = rsqrtf(var + 1e-6f);
            int row = qt*64 + nl0 + rr*8;
            size_t base = (size_t)(b*NP + row)*EP + h*64;
            #pragma unroll
            for (int nt = 0; nt < 8; nt++) {
                int col = nt*8 + 2*(lane & 3);
                float2 g2 = *(const float2*)(g_G + base + col);
                float x0 = (ret[nt][rr*2]   - mean)*inv * g2.x;
                float x1 = (ret[nt][rr*2+1] - mean)*inv * g2.y;
                uint32_t hh, ll;
                split_pair_h(x0, x1, hh, ll);
                *(uint32_t*)(g_RGh + base + col) = hh;
                *(uint32_t*)(g_RGl + base + col) = ll;
            }
        }
    }
}

// ---------------- launch ----------------
extern "C" void kernel_launch(void* const* d_in, const int* in_sizes, int n_in,
                              void* d_out, int out_size) {
    const float* query = (const float*)d_in[0];
    const float* key   = (const float*)d_in[1];
    const float* value = (const float*)d_in[2];
    const float* Wq = (const float*)d_in[3];
    const float* bq = (const float*)d_in[4];
    const float* Wk = (const float*)d_in[5];
    const float* bk = (const float*)d_in[6];
    const float* Wv = (const float*)d_in[7];
    const float* bv = (const float*)d_in[8];
    const float* Wg = (const float*)d_in[9];
    const float* bg = (const float*)d_in[10];
    const float* Wo = (const float*)d_in[11];
    const float* bo = (const float*)d_in[12];
    float* out = (float*)d_out;

    build_tables<<<(NP*32)/256, 256>>>();
    convert_in<<<dim3((MT*EP)/1024, 3), 256>>>(query, key, value);
    convert_w<<<dim3((EP*EP)/1024, 5), 256>>>(Wq, Wk, Wv, Wg, Wo);

    cudaFuncSetAttribute(qkvg_kernel, cudaFuncAttributeMaxDynamicSharedMemorySize, PROJ_SMEM);
    cudaFuncSetAttribute(out_kernel,  cudaFuncAttributeMaxDynamicSharedMemorySize, PROJ_SMEM);
    cudaFuncSetAttribute(retention_kernel, cudaFuncAttributeMaxDynamicSharedMemorySize, (int)RET_SMEM);

    qkvg_kernel<<<dim3(4, 64, 4), 256, PROJ_SMEM>>>(bq, bk, bv, bg);
    retention_kernel<<<dim3(16, 8, 2), 128, RET_SMEM>>>();
    out_kernel<<<dim3(4, 64, 1), 256, PROJ_SMEM>>>(bo, out);
}

// round 13
// speedup vs baseline: 1.3682x; 1.1090x over previous
#include <cuda_runtime.h>
#include <cuda_fp16.h>
#include <math.h>
#include <stdint.h>

#define NP 2048
#define EP 512
#define MT 4096

// ---------------- device scratch ----------------
__device__ __align__(16) float g_sin[NP*32];
__device__ __align__(16) float g_cos[NP*32];
__device__ __align__(16) float g_scale[NP*32];
__device__ __align__(16) __half g_INh[3][MT*EP];
__device__ __align__(16) __half g_INl[2][MT*EP];   // lo planes only for query,key
__device__ __align__(16) __half g_Wh[5][EP*EP];
__device__ __align__(16) __half g_Qh[MT*EP];
__device__ __align__(16) __half g_Kh[MT*EP];
__device__ __align__(16) __half g_Vh[MT*EP];
__device__ __align__(16) __half g_RGh[MT*EP];
__device__ __align__(16) float g_G[MT*EP];

// ---------------- helpers ----------------
__device__ __forceinline__ uint32_t smem_u32(const void* p) {
    uint32_t a;
    asm("{ .reg .u64 t; cvta.to.shared.u64 t, %1; cvt.u32.u64 %0, t; }" : "=r"(a) : "l"(p));
    return a;
}
__device__ __forceinline__ void ldsm4(uint32_t* r, uint32_t a) {
    asm volatile("ldmatrix.sync.aligned.m8n8.x4.shared.b16 {%0,%1,%2,%3}, [%4];"
        : "=r"(r[0]), "=r"(r[1]), "=r"(r[2]), "=r"(r[3]) : "r"(a));
}
__device__ __forceinline__ void ldsm4t(uint32_t* r, uint32_t a) {
    asm volatile("ldmatrix.sync.aligned.m8n8.x4.trans.shared.b16 {%0,%1,%2,%3}, [%4];"
        : "=r"(r[0]), "=r"(r[1]), "=r"(r[2]), "=r"(r[3]) : "r"(a));
}
__device__ __forceinline__ void mma_f16(float* c, const uint32_t* a, uint32_t b0, uint32_t b1) {
    asm volatile("mma.sync.aligned.m16n8k16.row.col.f32.f16.f16.f32 "
        "{%0,%1,%2,%3}, {%4,%5,%6,%7}, {%8,%9}, {%0,%1,%2,%3};"
        : "+f"(c[0]), "+f"(c[1]), "+f"(c[2]), "+f"(c[3])
        : "r"(a[0]), "r"(a[1]), "r"(a[2]), "r"(a[3]), "r"(b0), "r"(b1));
}
__device__ __forceinline__ void split_pair_h(float v0, float v1, uint32_t& hi, uint32_t& lo) {
    __half h0 = __float2half_rn(v0);
    __half h1 = __float2half_rn(v1);
    __half l0 = __float2half_rn(v0 - __half2float(h0));
    __half l1 = __float2half_rn(v1 - __half2float(h1));
    __half2 H = __halves2half2(h0, h1);
    __half2 L = __halves2half2(l0, l1);
    hi = *reinterpret_cast<uint32_t*>(&H);
    lo = *reinterpret_cast<uint32_t*>(&L);
}
__device__ __forceinline__ uint32_t pack_h(float v0, float v1) {
    __half2 H = __floats2half2_rn(v0, v1);
    return *reinterpret_cast<uint32_t*>(&H);
}
__device__ __forceinline__ void cp16(uint32_t sdst, const void* gsrc) {
    asm volatile("cp.async.cg.shared.global [%0], [%1], 16;" :: "r"(sdst), "l"(gsrc) : "memory");
}
#define CP_COMMIT() asm volatile("cp.async.commit_group;" ::: "memory")
#define CP_WAIT(N)  asm volatile("cp.async.wait_group %0;" :: "n"(N) : "memory")

// ---------------- xpos tables ----------------
__global__ void build_tables() {
    int idx = blockIdx.x * 256 + threadIdx.x;
    if (idx >= NP*32) return;
    int n = idx >> 5, j = idx & 31;
    float inv_freq = expf(-(float)j * (9.210340371976184f / 32.f));
    float s, c;
    sincosf((float)n * inv_freq, &s, &c);
    float xscale = (2.f*(float)j + 25.6f) / 89.6f;
    float power = ((float)n - 1024.f) * (1.f/512.f);
    g_sin[idx] = s; g_cos[idx] = c; g_scale[idx] = expf(power * logf(xscale));
}

// ---------------- pre-split / convert ----------------
__global__ void convert_in(const float* __restrict__ q, const float* __restrict__ k,
                           const float* __restrict__ v) {
    int z = blockIdx.y;
    const float* src = (z == 0) ? q : (z == 1) ? k : v;
    int idx = (blockIdx.x * 256 + threadIdx.x) * 4;
    float4 x = *(const float4*)(src + idx);
    uint32_t h0,l0,h1,l1;
    split_pair_h(x.x, x.y, h0, l0);
    split_pair_h(x.z, x.w, h1, l1);
    *(uint2*)(&g_INh[z][idx]) = make_uint2(h0, h1);
    if (z < 2)
        *(uint2*)(&g_INl[z][idx]) = make_uint2(l0, l1);
}
__global__ void convert_w(const float* __restrict__ w0, const float* __restrict__ w1,
                          const float* __restrict__ w2, const float* __restrict__ w3,
                          const float* __restrict__ w4) {
    int z = blockIdx.y;
    const float* src = (z == 0) ? w0 : (z == 1) ? w1 : (z == 2) ? w2 : (z == 3) ? w3 : w4;
    int idx = (blockIdx.x * 256 + threadIdx.x) * 4;
    float4 x = *(const float4*)(src + idx);
    *(uint2*)(&g_Wh[z][idx]) = make_uint2(pack_h(x.x, x.y), pack_h(x.z, x.w));
}

// ===== projection GEMM (fp16, M64xN128 tile, warp 32x32, 3-stage K32, 3 CTA/SM) =====
// stage 20480B: AH@0 (64x80B) AL@5120 BH@10240 (128x80B)
#define PSTG 20480
#define PROJ_SMEM (3*PSTG)

template<bool LO>
__device__ __forceinline__ void proj_load_stage(
    uint32_t sb, int stage,
    const __half* __restrict__ Ah, const __half* __restrict__ Al,
    const __half* __restrict__ Bh,
    int m0, int n0, int kc, int tid)
{
    uint32_t s0 = sb + stage * PSTG;
    {
        int row = tid >> 2, seg = tid & 3;
        uint32_t so = (uint32_t)row*80 + seg*16;
        size_t ga = (size_t)(m0 + row)*EP + kc*32 + seg*8;
        cp16(s0 +         so, Ah + ga);
        if (LO) cp16(s0 + 5120 + so, Al + ga);
    }
    #pragma unroll
    for (int i = 0; i < 2; i++) {
        int t = tid + i*256; int row = t >> 2, seg = t & 3;
        uint32_t so = (uint32_t)row*80 + seg*16;
        size_t gb = (size_t)(n0 + row)*EP + kc*32 + seg*8;
        cp16(s0 + 10240 + so, Bh + gb);
    }
}

template<bool LO>
__device__ __forceinline__ void proj_body(
    const __half* __restrict__ Ah, const __half* __restrict__ Al,
    const __half* __restrict__ Bh,
    const float* __restrict__ bias, int epi,
    float* Cf, __half* Ch, char* sm)
{
    const int tid = threadIdx.x, lane = tid & 31, wid = tid >> 5;
    const int wm = wid & 1, wn = wid >> 1;          // 2 m-warps x 4 n-warps
    const int n0 = blockIdx.x * 128, m0 = blockIdx.y * 64;
    const uint32_t sb = smem_u32(sm);
    float acc[2][4][4] = {};

    proj_load_stage<LO>(sb, 0, Ah, Al, Bh, m0, n0, 0, tid); CP_COMMIT();
    proj_load_stage<LO>(sb, 1, Ah, Al, Bh, m0, n0, 1, tid); CP_COMMIT();

    for (int kc = 0; kc < 16; kc++) {
        CP_WAIT(1);
        __syncthreads();
        if (kc + 2 < 16)
            proj_load_stage<LO>(sb, (kc + 2) % 3, Ah, Al, Bh, m0, n0, kc + 2, tid);
        CP_COMMIT();

        const uint32_t base = sb + (kc % 3) * PSTG;
        #pragma unroll
        for (int kk = 0; kk < 2; kk++) {
            uint32_t ah[2][4], al[2][4];
            #pragma unroll
            for (int mt = 0; mt < 2; mt++) {
                uint32_t off = (uint32_t)(wm*32 + mt*16 + (lane & 15))*80 + kk*32 + ((lane >> 4) & 1)*16;
                ldsm4(ah[mt], base + off);
                if (LO) ldsm4(al[mt], base + 5120 + off);
            }
            uint32_t bh[2][4];
            #pragma unroll
            for (int jt = 0; jt < 2; jt++) {
                uint32_t off = (uint32_t)(wn*32 + jt*16 + (lane & 7) + ((lane & 16) ? 8 : 0))*80
                             + kk*32 + ((lane & 8) ? 16 : 0);
                ldsm4(bh[jt], base + 10240 + off);
            }
            #pragma unroll
            for (int mt = 0; mt < 2; mt++)
                #pragma unroll
                for (int nt = 0; nt < 4; nt++) {
                    int jt = nt >> 1, o = (nt & 1)*2;
                    mma_f16(acc[mt][nt], ah[mt], bh[jt][o], bh[jt][o+1]);
                    if (LO) mma_f16(acc[mt][nt], al[mt], bh[jt][o], bh[jt][o+1]);
                }
        }
    }

    #pragma unroll
    for (int mt = 0; mt < 2; mt++) {
        #pragma unroll
        for (int rr = 0; rr < 2; rr++) {
            int row = m0 + wm*32 + mt*16 + (lane >> 2) + rr*8;
            int npos = row & (NP - 1);
            #pragma unroll
            for (int nt = 0; nt < 4; nt++) {
                int col = n0 + wn*32 + nt*8 + 2*(lane & 3);
                float x0 = acc[mt][nt][rr*2]     + bias[col];
                float x1 = acc[mt][nt][rr*2 + 1] + bias[col + 1];
                if (epi == 1) {
                    x0 = x0 / (1.f + expf(-x0));
                    x1 = x1 / (1.f + expf(-x1));
                } else if (epi == 2 || epi == 3) {
                    int j2 = (col & 63) >> 1;
                    float sn = g_sin[npos*32 + j2];
                    float cs = g_cos[npos*32 + j2];
                    float sc = g_scale[npos*32 + j2];
                    if (epi == 3) sc = 1.f / sc;
                    float s = sn * sc, c = cs * sc;
                    float y0 = x0 * c - x1 * s;
                    float y1 = x1 * c + x0 * s;
                    if (epi == 3) { y0 *= 0.125f; y1 *= 0.125f; }
                    x0 = y0; x1 = y1;
                }
                size_t off = (size_t)row*EP + col;
                if (Cf) {
                    *(float2*)(Cf + off) = make_float2(x0, x1);
                } else {
                    *(uint32_t*)(Ch + off) = pack_h(x0, x1);
                }
            }
        }
    }
}

__global__ void __launch_bounds__(256, 3) qkvg_kernel(
    const float* __restrict__ bq, const float* __restrict__ bk,
    const float* __restrict__ bv, const float* __restrict__ bg)
{
    extern __shared__ char sm[];
    const int z = blockIdx.z;
    const float* bias = (z == 0) ? bq : (z == 1) ? bk : (z == 2) ? bv : bg;
    if (z == 0) {
        proj_body<true >(g_INh[0], g_INl[0], g_Wh[0], bias, 2, (float*)0, g_Qh, sm);
    } else if (z == 1) {
        proj_body<true >(g_INh[1], g_INl[1], g_Wh[1], bias, 3, (float*)0, g_Kh, sm);
    } else if (z == 2) {
        proj_body<false>(g_INh[2], (const __half*)0, g_Wh[2], bias, 0, (float*)0, g_Vh, sm);
    } else {
        proj_body<false>(g_INh[0], (const __half*)0, g_Wh[3], bias, 1, g_G, (__half*)0, sm);
    }
}

__global__ void __launch_bounds__(256, 3) out_kernel(const float* __restrict__ bo,
                                                     float* __restrict__ out)
{
    extern __shared__ char sm[];
    proj_body<false>(g_RGh, (const __half*)0, g_Wh[4], bo, 0, out, (__half*)0, sm);
}

// ========== retention (fp16 single-plane mma, 64-row q-tiles, 3-stage KV, 3 CTA/SM) ====
// smem: QH@0 (64x144) | KV stage s @ 9216+s*18432 {KH+0, VH+9216}
#define RSM_QH 0u
#define RSM_KV 9216u
#define KVSTG 18432u
#define RET_SMEM (9216u + 3u*18432u)   // 64512

__device__ __forceinline__ void kv_load_stage(uint32_t sb, int stage, int b, int h,
                                              int st, int tid)
{
    uint32_t s0 = sb + RSM_KV + (uint32_t)stage * KVSTG;
    #pragma unroll
    for (int i = 0; i < 4; i++) {
        int t = tid + i*128; int row = t >> 3, seg = t & 7;
        uint32_t so = (uint32_t)row*144 + seg*16;
        size_t ga = (size_t)(b*NP + st*64 + row)*EP + h*64 + seg*8;
        cp16(s0 +        so, g_Kh + ga);
        cp16(s0 + 9216 + so, g_Vh + ga);
    }
}

__global__ void __launch_bounds__(128, 3) retention_kernel()
{
    extern __shared__ char sm[];
    const int tid = threadIdx.x, lane = tid & 31, wid = tid >> 5;   // wid 0..3
    const int h = blockIdx.y, b = blockIdx.z;
    const uint32_t sb = smem_u32(sm);

    const float gamma = 1.f - expf(-(3.465735902799726f + 0.396084103177426f * (float)h));
    const float l2g = log2f(gamma);

    float colf[16];
    #pragma unroll
    for (int nt = 0; nt < 8; nt++) {
        int sl = nt*8 + 2*(lane & 3);
        colf[nt*2]   = exp2f(-l2g * (float)sl);
        colf[nt*2+1] = exp2f(-l2g * (float)(sl + 1));
    }
    const int nl0 = wid*16 + (lane >> 2);

    for (int phase = 0; phase < 2; phase++) {
        const int qt = phase ? (int)blockIdx.x : 31 - (int)blockIdx.x;
        const int n_st = qt + 1;

        // load Q tile (64 x 64, fp16 single plane)
        #pragma unroll
        for (int i = 0; i < 4; i++) {
            int t = tid + i*128; int row = t >> 3, seg = t & 7;
            size_t ga = (size_t)(b*NP + qt*64 + row)*EP + h*64 + seg*8;
            *(uint4*)(sm + RSM_QH + row*144 + seg*16) = *(const uint4*)(g_Qh + ga);
        }
        __syncthreads();   // prev-phase compute done + Q visible

        kv_load_stage(sb, 0, b, h, 0, tid); CP_COMMIT();
        if (n_st > 1) kv_load_stage(sb, 1, b, h, 1, tid);
        CP_COMMIT();

        uint32_t qh[4][4];
        #pragma unroll
        for (int kk = 0; kk < 4; kk++) {
            uint32_t off = (uint32_t)(wid*16 + (lane & 15))*144 + kk*32 + ((lane >> 4) & 1)*16;
            ldsm4(qh[kk], sb + RSM_QH + off);
        }

        float ret[8][4] = {};

        for (int st = 0; st < n_st; st++) {
            CP_WAIT(1);
            __syncthreads();
            if (st + 2 < n_st) kv_load_stage(sb, (st + 2) % 3, b, h, st + 2, tid);
            CP_COMMIT();

            const uint32_t kvb = sb + RSM_KV + (uint32_t)(st % 3) * KVSTG;

            // gemm1: sim = Q K^T (k = 64), fp16 single plane
            float simf[8][4] = {};
            #pragma unroll
            for (int kk = 0; kk < 4; kk++) {
                uint32_t bh[4][4];
                #pragma unroll
                for (int jt = 0; jt < 4; jt++) {
                    uint32_t off = (uint32_t)(jt*16 + (lane & 7) + ((lane & 16) ? 8 : 0))*144
                                 + kk*32 + ((lane & 8) ? 16 : 0);
                    ldsm4(bh[jt], kvb + off);
                }
                #pragma unroll
                for (int nt = 0; nt < 8; nt++) {
                    int jt = nt >> 1, o = (nt & 1)*2;
                    mma_f16(simf[nt], qh[kk], bh[jt][o], bh[jt][o+1]);
                }
            }

            // decay + mask + pack -> fp16 A-fragments of gemm2 (registers only)
            const int db = qt*64 - st*64;
            const float brf0 = exp2f(l2g * (float)(db + nl0));
            const float brf1 = exp2f(l2g * (float)(db + nl0 + 8));
            uint32_t pa[8], pb[8];
            #pragma unroll
            for (int nt = 0; nt < 8; nt++) {
                int sl0 = nt*8 + 2*(lane & 3);
                float v00 = (db + nl0 - sl0     >= 0) ? simf[nt][0]*brf0*colf[nt*2]   : 0.f;
                float v01 = (db + nl0 - sl0 - 1 >= 0) ? simf[nt][1]*brf0*colf[nt*2+1] : 0.f;
                float v10 = (db + nl0 + 8 - sl0     >= 0) ? simf[nt][2]*brf1*colf[nt*2]   : 0.f;
                float v11 = (db + nl0 + 8 - sl0 - 1 >= 0) ? simf[nt][3]*brf1*colf[nt*2+1] : 0.f;
                pa[nt] = pack_h(v00, v01);
                pb[nt] = pack_h(v10, v11);
            }

            // gemm2: ret += sim @ V (fp16 single plane)
            #pragma unroll
            for (int kk = 0; kk < 4; kk++) {
                uint32_t ah2[4] = { pa[2*kk], pb[2*kk], pa[2*kk+1], pb[2*kk+1] };
                uint32_t bh[4][4];
                #pragma unroll
                for (int dt = 0; dt < 4; dt++) {
                    uint32_t off = (uint32_t)(kk*16 + (lane & 15))*144 + dt*32 + ((lane >> 4) & 1)*16;
                    ldsm4t(bh[dt], kvb + 9216 + off);
                }
                #pragma unroll
                for (int nt = 0; nt < 8; nt++) {
                    int dt = nt >> 1, o = (nt & 1)*2;
                    mma_f16(ret[nt], ah2, bh[dt][o], bh[dt][o+1]);
                }
            }
        }

        // groupnorm + gate + write fp16 (single plane)
        #pragma unroll
        for (int rr = 0; rr < 2; rr++) {
            float s1 = 0.f, s2 = 0.f;
            #pragma unroll
            for (int nt = 0; nt < 8; nt++) {
                float a = ret[nt][rr*2], c = ret[nt][rr*2+1];
                s1 += a + c; s2 += a*a + c*c;
            }
            s1 += __shfl_xor_sync(0xffffffffu, s1, 1); s2 += __shfl_xor_sync(0xffffffffu, s2, 1);
            s1 += __shfl_xor_sync(0xffffffffu, s1, 2); s2 += __shfl_xor_sync(0xffffffffu, s2, 2);
            float mean = s1 * (1.f/64.f);
            float var  = s2 * (1.f/64.f) - mean*mean;
            float inv  = rsqrtf(var + 1e-6f);
            int row = qt*64 + nl0 + rr*8;
            size_t base = (size_t)(b*NP + row)*EP + h*64;
            #pragma unroll
            for (int nt = 0; nt < 8; nt++) {
                int col = nt*8 + 2*(lane & 3);
                float2 g2 = *(const float2*)(g_G + base + col);
                float x0 = (ret[nt][rr*2]   - mean)*inv * g2.x;
                float x1 = (ret[nt][rr*2+1] - mean)*inv * g2.y;
                *(uint32_t*)(g_RGh + base + col) = pack_h(x0, x1);
            }
        }
    }
}

// ---------------- launch ----------------
extern "C" void kernel_launch(void* const* d_in, const int* in_sizes, int n_in,
                              void* d_out, int out_size) {
    const float* query = (const float*)d_in[0];
    const float* key   = (const float*)d_in[1];
    const float* value = (const float*)d_in[2];
    const float* Wq = (const float*)d_in[3];
    const float* bq = (const float*)d_in[4];
    const float* Wk = (const float*)d_in[5];
    const float* bk = (const float*)d_in[6];
    const float* Wv = (const float*)d_in[7];
    const float* bv = (const float*)d_in[8];
    const float* Wg = (const float*)d_in[9];
    const float* bg = (const float*)d_in[10];
    const float* Wo = (const float*)d_in[11];
    const float* bo = (const float*)d_in[12];
    float* out = (float*)d_out;

    build_tables<<<(NP*32)/256, 256>>>();
    convert_in<<<dim3((MT*EP)/1024, 3), 256>>>(query, key, value);
    convert_w<<<dim3((EP*EP)/1024, 5), 256>>>(Wq, Wk, Wv, Wg, Wo);

    cudaFuncSetAttribute(qkvg_kernel, cudaFuncAttributeMaxDynamicSharedMemorySize, PROJ_SMEM);
    cudaFuncSetAttribute(out_kernel,  cudaFuncAttributeMaxDynamicSharedMemorySize, PROJ_SMEM);
    cudaFuncSetAttribute(retention_kernel, cudaFuncAttributeMaxDynamicSharedMemorySize, (int)RET_SMEM);

    qkvg_kernel<<<dim3(4, 64, 4), 256, PROJ_SMEM>>>(bq, bk, bv, bg);
    retention_kernel<<<dim3(16, 8, 2), 128, RET_SMEM>>>();
    out_kernel<<<dim3(4, 64, 1), 256, PROJ_SMEM>>>(bo, out);
}

// round 14
// speedup vs baseline: 1.5804x; 1.1551x over previous
#include <cuda_runtime.h>
#include <cuda_fp16.h>
#include <math.h>
#include <stdint.h>

#define NP 2048
#define EP 512
#define MT 4096

// ---------------- device scratch ----------------
__device__ __align__(16) float g_sin[NP*32];
__device__ __align__(16) float g_cos[NP*32];
__device__ __align__(16) float g_scale[NP*32];
__device__ __align__(16) __half g_INh[3][MT*EP];
__device__ __align__(16) __half g_Wh[5][EP*EP];
__device__ __align__(16) __half g_Qh[MT*EP];
__device__ __align__(16) __half g_Kh[MT*EP];
__device__ __align__(16) __half g_Vh[MT*EP];
__device__ __align__(16) __half g_RGh[MT*EP];
__device__ __align__(16) float g_G[MT*EP];

// ---------------- helpers ----------------
__device__ __forceinline__ uint32_t smem_u32(const void* p) {
    uint32_t a;
    asm("{ .reg .u64 t; cvta.to.shared.u64 t, %1; cvt.u32.u64 %0, t; }" : "=r"(a) : "l"(p));
    return a;
}
__device__ __forceinline__ void ldsm4(uint32_t* r, uint32_t a) {
    asm volatile("ldmatrix.sync.aligned.m8n8.x4.shared.b16 {%0,%1,%2,%3}, [%4];"
        : "=r"(r[0]), "=r"(r[1]), "=r"(r[2]), "=r"(r[3]) : "r"(a));
}
__device__ __forceinline__ void ldsm4t(uint32_t* r, uint32_t a) {
    asm volatile("ldmatrix.sync.aligned.m8n8.x4.trans.shared.b16 {%0,%1,%2,%3}, [%4];"
        : "=r"(r[0]), "=r"(r[1]), "=r"(r[2]), "=r"(r[3]) : "r"(a));
}
__device__ __forceinline__ void mma_f16(float* c, const uint32_t* a, uint32_t b0, uint32_t b1) {
    asm volatile("mma.sync.aligned.m16n8k16.row.col.f32.f16.f16.f32 "
        "{%0,%1,%2,%3}, {%4,%5,%6,%7}, {%8,%9}, {%0,%1,%2,%3};"
        : "+f"(c[0]), "+f"(c[1]), "+f"(c[2]), "+f"(c[3])
        : "r"(a[0]), "r"(a[1]), "r"(a[2]), "r"(a[3]), "r"(b0), "r"(b1));
}
__device__ __forceinline__ uint32_t pack_h(float v0, float v1) {
    __half2 H = __floats2half2_rn(v0, v1);
    return *reinterpret_cast<uint32_t*>(&H);
}
__device__ __forceinline__ void cp16(uint32_t sdst, const void* gsrc) {
    asm volatile("cp.async.cg.shared.global [%0], [%1], 16;" :: "r"(sdst), "l"(gsrc) : "memory");
}
#define CP_COMMIT() asm volatile("cp.async.commit_group;" ::: "memory")
#define CP_WAIT(N)  asm volatile("cp.async.wait_group %0;" :: "n"(N) : "memory")

// ---------------- fused setup: converts + xpos tables ----------------
// blocks [0, 6144): inputs (3 x 2048 blocks), [6144, 7424): weights (5 x 256),
// [7424, 7680): xpos tables (256 blocks).
__global__ void setup_kernel(
    const float* __restrict__ q, const float* __restrict__ k, const float* __restrict__ v,
    const float* __restrict__ w0, const float* __restrict__ w1, const float* __restrict__ w2,
    const float* __restrict__ w3, const float* __restrict__ w4)
{
    int bid = blockIdx.x, tid = threadIdx.x;
    if (bid < 6144) {
        int z = bid >> 11;
        int idx = ((bid & 2047) * 256 + tid) * 4;
        const float* src = (z == 0) ? q : (z == 1) ? k : v;
        float4 x = *(const float4*)(src + idx);
        *(uint2*)(&g_INh[z][idx]) = make_uint2(pack_h(x.x, x.y), pack_h(x.z, x.w));
    } else if (bid < 7424) {
        int r = bid - 6144;
        int z = r >> 8;
        int idx = ((r & 255) * 256 + tid) * 4;
        const float* src = (z == 0) ? w0 : (z == 1) ? w1 : (z == 2) ? w2 : (z == 3) ? w3 : w4;
        float4 x = *(const float4*)(src + idx);
        *(uint2*)(&g_Wh[z][idx]) = make_uint2(pack_h(x.x, x.y), pack_h(x.z, x.w));
    } else {
        int idx = (bid - 7424) * 256 + tid;   // [0, 65536)
        int n = idx >> 5, j = idx & 31;
        float inv_freq = expf(-(float)j * (9.210340371976184f / 32.f));
        float s, c;
        sincosf((float)n * inv_freq, &s, &c);
        float xscale = (2.f*(float)j + 25.6f) / 89.6f;
        float power = ((float)n - 1024.f) * (1.f/512.f);
        g_sin[idx] = s; g_cos[idx] = c; g_scale[idx] = expf(power * logf(xscale));
    }
}

// ===== projection GEMM (fp16 single-plane, M64xN128, warp 32x32, 3-stage K32, 3 CTA/SM) =====
// stage 15360B: AH@0 (64x80B) BH@5120 (128x80B)
#define PSTG 15360
#define PROJ_SMEM (3*PSTG)

__device__ __forceinline__ void proj_load_stage(
    uint32_t sb, int stage,
    const __half* __restrict__ Ah, const __half* __restrict__ Bh,
    int m0, int n0, int kc, int tid)
{
    uint32_t s0 = sb + stage * PSTG;
    {
        int row = tid >> 2, seg = tid & 3;
        uint32_t so = (uint32_t)row*80 + seg*16;
        size_t ga = (size_t)(m0 + row)*EP + kc*32 + seg*8;
        cp16(s0 + so, Ah + ga);
    }
    #pragma unroll
    for (int i = 0; i < 2; i++) {
        int t = tid + i*256; int row = t >> 2, seg = t & 3;
        uint32_t so = (uint32_t)row*80 + seg*16;
        size_t gb = (size_t)(n0 + row)*EP + kc*32 + seg*8;
        cp16(s0 + 5120 + so, Bh + gb);
    }
}

__device__ __forceinline__ void proj_body(
    const __half* __restrict__ Ah, const __half* __restrict__ Bh,
    const float* __restrict__ bias, int epi,
    float* Cf, __half* Ch, char* sm)
{
    const int tid = threadIdx.x, lane = tid & 31, wid = tid >> 5;
    const int wm = wid & 1, wn = wid >> 1;          // 2 m-warps x 4 n-warps
    const int n0 = blockIdx.x * 128, m0 = blockIdx.y * 64;
    const uint32_t sb = smem_u32(sm);
    float acc[2][4][4] = {};

    proj_load_stage(sb, 0, Ah, Bh, m0, n0, 0, tid); CP_COMMIT();
    proj_load_stage(sb, 1, Ah, Bh, m0, n0, 1, tid); CP_COMMIT();

    for (int kc = 0; kc < 16; kc++) {
        CP_WAIT(1);
        __syncthreads();
        if (kc + 2 < 16)
            proj_load_stage(sb, (kc + 2) % 3, Ah, Bh, m0, n0, kc + 2, tid);
        CP_COMMIT();

        const uint32_t base = sb + (kc % 3) * PSTG;
        #pragma unroll
        for (int kk = 0; kk < 2; kk++) {
            uint32_t ah[2][4];
            #pragma unroll
            for (int mt = 0; mt < 2; mt++) {
                uint32_t off = (uint32_t)(wm*32 + mt*16 + (lane & 15))*80 + kk*32 + ((lane >> 4) & 1)*16;
                ldsm4(ah[mt], base + off);
            }
            uint32_t bh[2][4];
            #pragma unroll
            for (int jt = 0; jt < 2; jt++) {
                uint32_t off = (uint32_t)(wn*32 + jt*16 + (lane & 7) + ((lane & 16) ? 8 : 0))*80
                             + kk*32 + ((lane & 8) ? 16 : 0);
                ldsm4(bh[jt], base + 5120 + off);
            }
            #pragma unroll
            for (int mt = 0; mt < 2; mt++)
                #pragma unroll
                for (int nt = 0; nt < 4; nt++) {
                    int jt = nt >> 1, o = (nt & 1)*2;
                    mma_f16(acc[mt][nt], ah[mt], bh[jt][o], bh[jt][o+1]);
                }
        }
    }

    #pragma unroll
    for (int mt = 0; mt < 2; mt++) {
        #pragma unroll
        for (int rr = 0; rr < 2; rr++) {
            int row = m0 + wm*32 + mt*16 + (lane >> 2) + rr*8;
            int npos = row & (NP - 1);
            #pragma unroll
            for (int nt = 0; nt < 4; nt++) {
                int col = n0 + wn*32 + nt*8 + 2*(lane & 3);
                float x0 = acc[mt][nt][rr*2]     + bias[col];
                float x1 = acc[mt][nt][rr*2 + 1] + bias[col + 1];
                if (epi == 1) {
                    x0 = x0 / (1.f + expf(-x0));
                    x1 = x1 / (1.f + expf(-x1));
                } else if (epi == 2 || epi == 3) {
                    int j2 = (col & 63) >> 1;
                    float sn = g_sin[npos*32 + j2];
                    float cs = g_cos[npos*32 + j2];
                    float sc = g_scale[npos*32 + j2];
                    if (epi == 3) sc = 1.f / sc;
                    float s = sn * sc, c = cs * sc;
                    float y0 = x0 * c - x1 * s;
                    float y1 = x1 * c + x0 * s;
                    if (epi == 3) { y0 *= 0.125f; y1 *= 0.125f; }
                    x0 = y0; x1 = y1;
                }
                size_t off = (size_t)row*EP + col;
                if (Cf) {
                    *(float2*)(Cf + off) = make_float2(x0, x1);
                } else {
                    *(uint32_t*)(Ch + off) = pack_h(x0, x1);
                }
            }
        }
    }
}

__global__ void __launch_bounds__(256, 3) qkvg_kernel(
    const float* __restrict__ bq, const float* __restrict__ bk,
    const float* __restrict__ bv, const float* __restrict__ bg)
{
    extern __shared__ char sm[];
    const int z = blockIdx.z;
    if (z == 0) {
        proj_body(g_INh[0], g_Wh[0], bq, 2, (float*)0, g_Qh, sm);
    } else if (z == 1) {
        proj_body(g_INh[1], g_Wh[1], bk, 3, (float*)0, g_Kh, sm);
    } else if (z == 2) {
        proj_body(g_INh[2], g_Wh[2], bv, 0, (float*)0, g_Vh, sm);
    } else {
        proj_body(g_INh[0], g_Wh[3], bg, 1, g_G, (__half*)0, sm);
    }
}

__global__ void __launch_bounds__(256, 3) out_kernel(const float* __restrict__ bo,
                                                     float* __restrict__ out)
{
    extern __shared__ char sm[];
    proj_body(g_RGh, g_Wh[4], bo, 0, out, (__half*)0, sm);
}

// ========== retention (fp16 single-plane mma, 64-row q-tiles, 3-stage KV, 3 CTA/SM) ====
// smem: QH@0 (64x144) | KV stage s @ 9216+s*18432 {KH+0, VH+9216}
#define RSM_QH 0u
#define RSM_KV 9216u
#define KVSTG 18432u
#define RET_SMEM (9216u + 3u*18432u)   // 64512

__device__ __forceinline__ void kv_load_stage(uint32_t sb, int stage, int b, int h,
                                              int st, int tid)
{
    uint32_t s0 = sb + RSM_KV + (uint32_t)stage * KVSTG;
    #pragma unroll
    for (int i = 0; i < 4; i++) {
        int t = tid + i*128; int row = t >> 3, seg = t & 7;
        uint32_t so = (uint32_t)row*144 + seg*16;
        size_t ga = (size_t)(b*NP + st*64 + row)*EP + h*64 + seg*8;
        cp16(s0 +        so, g_Kh + ga);
        cp16(s0 + 9216 + so, g_Vh + ga);
    }
}

__global__ void __launch_bounds__(128, 3) retention_kernel()
{
    extern __shared__ char sm[];
    const int tid = threadIdx.x, lane = tid & 31, wid = tid >> 5;   // wid 0..3
    const int h = blockIdx.y, b = blockIdx.z;
    const uint32_t sb = smem_u32(sm);

    const float gamma = 1.f - expf(-(3.465735902799726f + 0.396084103177426f * (float)h));
    const float l2g = log2f(gamma);

    float colf[16];
    #pragma unroll
    for (int nt = 0; nt < 8; nt++) {
        int sl = nt*8 + 2*(lane & 3);
        colf[nt*2]   = exp2f(-l2g * (float)sl);
        colf[nt*2+1] = exp2f(-l2g * (float)(sl + 1));
    }
    const int nl0 = wid*16 + (lane >> 2);

    for (int phase = 0; phase < 2; phase++) {
        const int qt = phase ? (int)blockIdx.x : 31 - (int)blockIdx.x;
        const int n_st = qt + 1;

        // load Q tile (64 x 64, fp16 single plane)
        #pragma unroll
        for (int i = 0; i < 4; i++) {
            int t = tid + i*128; int row = t >> 3, seg = t & 7;
            size_t ga = (size_t)(b*NP + qt*64 + row)*EP + h*64 + seg*8;
            *(uint4*)(sm + RSM_QH + row*144 + seg*16) = *(const uint4*)(g_Qh + ga);
        }
        __syncthreads();   // prev-phase compute done + Q visible

        kv_load_stage(sb, 0, b, h, 0, tid); CP_COMMIT();
        if (n_st > 1) kv_load_stage(sb, 1, b, h, 1, tid);
        CP_COMMIT();

        uint32_t qh[4][4];
        #pragma unroll
        for (int kk = 0; kk < 4; kk++) {
            uint32_t off = (uint32_t)(wid*16 + (lane & 15))*144 + kk*32 + ((lane >> 4) & 1)*16;
            ldsm4(qh[kk], sb + RSM_QH + off);
        }

        float ret[8][4] = {};

        for (int st = 0; st < n_st; st++) {
            CP_WAIT(1);
            __syncthreads();
            if (st + 2 < n_st) kv_load_stage(sb, (st + 2) % 3, b, h, st + 2, tid);
            CP_COMMIT();

            const uint32_t kvb = sb + RSM_KV + (uint32_t)(st % 3) * KVSTG;

            // gemm1: sim = Q K^T (k = 64)
            float simf[8][4] = {};
            #pragma unroll
            for (int kk = 0; kk < 4; kk++) {
                uint32_t bh[4][4];
                #pragma unroll
                for (int jt = 0; jt < 4; jt++) {
                    uint32_t off = (uint32_t)(jt*16 + (lane & 7) + ((lane & 16) ? 8 : 0))*144
                                 + kk*32 + ((lane & 8) ? 16 : 0);
                    ldsm4(bh[jt], kvb + off);
                }
                #pragma unroll
                for (int nt = 0; nt < 8; nt++) {
                    int jt = nt >> 1, o = (nt & 1)*2;
                    mma_f16(simf[nt], qh[kk], bh[jt][o], bh[jt][o+1]);
                }
            }

            // decay + mask + pack -> fp16 A-fragments of gemm2 (registers only)
            const int db = qt*64 - st*64;
            const float brf0 = exp2f(l2g * (float)(db + nl0));
            const float brf1 = exp2f(l2g * (float)(db + nl0 + 8));
            uint32_t pa[8], pb[8];
            #pragma unroll
            for (int nt = 0; nt < 8; nt++) {
                int sl0 = nt*8 + 2*(lane & 3);
                float v00 = (db + nl0 - sl0     >= 0) ? simf[nt][0]*brf0*colf[nt*2]   : 0.f;
                float v01 = (db + nl0 - sl0 - 1 >= 0) ? simf[nt][1]*brf0*colf[nt*2+1] : 0.f;
                float v10 = (db + nl0 + 8 - sl0     >= 0) ? simf[nt][2]*brf1*colf[nt*2]   : 0.f;
                float v11 = (db + nl0 + 8 - sl0 - 1 >= 0) ? simf[nt][3]*brf1*colf[nt*2+1] : 0.f;
                pa[nt] = pack_h(v00, v01);
                pb[nt] = pack_h(v10, v11);
            }

            // gemm2: ret += sim @ V
            #pragma unroll
            for (int kk = 0; kk < 4; kk++) {
                uint32_t ah2[4] = { pa[2*kk], pb[2*kk], pa[2*kk+1], pb[2*kk+1] };
                uint32_t bh[4][4];
                #pragma unroll
                for (int dt = 0; dt < 4; dt++) {
                    uint32_t off = (uint32_t)(kk*16 + (lane & 15))*144 + dt*32 + ((lane >> 4) & 1)*16;
                    ldsm4t(bh[dt], kvb + 9216 + off);
                }
                #pragma unroll
                for (int nt = 0; nt < 8; nt++) {
                    int dt = nt >> 1, o = (nt & 1)*2;
                    mma_f16(ret[nt], ah2, bh[dt][o], bh[dt][o+1]);
                }
            }
        }

        // groupnorm + gate + write fp16 (single plane)
        #pragma unroll
        for (int rr = 0; rr < 2; rr++) {
            float s1 = 0.f, s2 = 0.f;
            #pragma unroll
            for (int nt = 0; nt < 8; nt++) {
                float a = ret[nt][rr*2], c = ret[nt][rr*2+1];
                s1 += a + c; s2 += a*a + c*c;
            }
            s1 += __shfl_xor_sync(0xffffffffu, s1, 1); s2 += __shfl_xor_sync(0xffffffffu, s2, 1);
            s1 += __shfl_xor_sync(0xffffffffu, s1, 2); s2 += __shfl_xor_sync(0xffffffffu, s2, 2);
            float mean = s1 * (1.f/64.f);
            float var  = s2 * (1.f/64.f) - mean*mean;
            float inv  = rsqrtf(var + 1e-6f);
            int row = qt*64 + nl0 + rr*8;
            size_t base = (size_t)(b*NP + row)*EP + h*64;
            #pragma unroll
            for (int nt = 0; nt < 8; nt++) {
                int col = nt*8 + 2*(lane & 3);
                float2 g2 = *(const float2*)(g_G + base + col);
                float x0 = (ret[nt][rr*2]   - mean)*inv * g2.x;
                float x1 = (ret[nt][rr*2+1] - mean)*inv * g2.y;
                *(uint32_t*)(g_RGh + base + col) = pack_h(x0, x1);
            }
        }
    }
}

// ---------------- launch ----------------
extern "C" void kernel_launch(void* const* d_in, const int* in_sizes, int n_in,
                              void* d_out, int out_size) {
    const float* query = (const float*)d_in[0];
    const float* key   = (const float*)d_in[1];
    const float* value = (const float*)d_in[2];
    const float* Wq = (const float*)d_in[3];
    const float* bq = (const float*)d_in[4];
    const float* Wk = (const float*)d_in[5];
    const float* bk = (const float*)d_in[6];
    const float* Wv = (const float*)d_in[7];
    const float* bv = (const float*)d_in[8];
    const float* Wg = (const float*)d_in[9];
    const float* bg = (const float*)d_in[10];
    const float* Wo = (const float*)d_in[11];
    const float* bo = (const float*)d_in[12];
    float* out = (float*)d_out;

    setup_kernel<<<7680, 256>>>(query, key, value, Wq, Wk, Wv, Wg, Wo);

    cudaFuncSetAttribute(qkvg_kernel, cudaFuncAttributeMaxDynamicSharedMemorySize, PROJ_SMEM);
    cudaFuncSetAttribute(out_kernel,  cudaFuncAttributeMaxDynamicSharedMemorySize, PROJ_SMEM);
    cudaFuncSetAttribute(retention_kernel, cudaFuncAttributeMaxDynamicSharedMemorySize, (int)RET_SMEM);

    qkvg_kernel<<<dim3(4, 64, 4), 256, PROJ_SMEM>>>(bq, bk, bv, bg);
    retention_kernel<<<dim3(16, 8, 2), 128, RET_SMEM>>>();
    out_kernel<<<dim3(4, 64, 1), 256, PROJ_SMEM>>>(bo, out);
}